// round 13
// baseline (speedup 1.0000x reference)
#include <cuda_runtime.h>
#include <cuda_bf16.h>
#include <math.h>
#include <stdint.h>

#define NB 8
#define NP 1024
#define ND 64
#define GAMMA 10.0f
#define MARGIN 0.1f
#define QSCALE 65535.0f
#define IQSCALE (1.0f / 65535.0f)

// ================= device scratch =================
__device__ __nv_bfloat16 d_hi[6 * NB * NP * ND];
__device__ __nv_bfloat16 d_lo[2 * NB * NP * ND];     // lo only for x1n, x2n
__device__ float d_C[NB * NP * NP];                  // sim S (32 MB), dead after finalize
__device__ unsigned short d_Cq[NB * NP * NP];        // u16 cost (16 MB)
__device__ unsigned short d_CTq[NB * NP * NP];       // u16 transposed cost (16 MB)
__device__ float d_r[NB * NP];
__device__ float d_c[NB * NP];
__device__ float d_fs[NB * NP];                      // init row sums  e^{-C/9}
__device__ float d_gs[NB * NP];                      // init col sums  e^{-C/9}
__device__ float d_f[2][NB * NP];
__device__ float d_g[2][NB * NP];
__device__ double d_hinge;
__device__ double d_scon;

// ================= helpers =================
__device__ __forceinline__ uint32_t smem_u32(const void* p) {
    uint32_t a;
    asm("{ .reg .u64 t; cvta.to.shared.u64 t, %1; cvt.u32.u64 %0, t; }" : "=r"(a) : "l"(p));
    return a;
}
__device__ __forceinline__ uint32_t sw128(uint32_t off) { return off ^ ((off >> 3) & 0x70); }

__device__ __forceinline__ void ldsm_x4(uint32_t* r, uint32_t addr) {
    asm volatile("ldmatrix.sync.aligned.m8n8.x4.shared.b16 {%0,%1,%2,%3}, [%4];"
        : "=r"(r[0]), "=r"(r[1]), "=r"(r[2]), "=r"(r[3]) : "r"(addr));
}
__device__ __forceinline__ void ldsm_x2(uint32_t* r, uint32_t addr) {
    asm volatile("ldmatrix.sync.aligned.m8n8.x2.shared.b16 {%0,%1}, [%2];"
        : "=r"(r[0]), "=r"(r[1]) : "r"(addr));
}
__device__ __forceinline__ void mma_bf16(float* d, const uint32_t* a, const uint32_t* b) {
    asm volatile("mma.sync.aligned.m16n8k16.row.col.f32.bf16.bf16.f32 "
        "{%0,%1,%2,%3}, {%4,%5,%6,%7}, {%8,%9}, {%0,%1,%2,%3};"
        : "+f"(d[0]), "+f"(d[1]), "+f"(d[2]), "+f"(d[3])
        : "r"(a[0]), "r"(a[1]), "r"(a[2]), "r"(a[3]), "r"(b[0]), "r"(b[1]));
}
__device__ __forceinline__ unsigned short quant(float v) {
    return (unsigned short)__float2uint_rn(fminf(fmaxf(v, 0.f), 1.f) * QSCALE);
}

// ================= normalize + hi/lo split (block 6144 = reset) =================
__global__ void norm_split(const float* __restrict__ x1, const float* __restrict__ x2,
                           const float* __restrict__ x3, const float* __restrict__ x4) {
    if (blockIdx.x == 6144) {
        int tid = threadIdx.x;
        for (int i = tid; i < NB * NP; i += 256) {
            d_r[i] = 0.f; d_c[i] = 0.f; d_fs[i] = 0.f; d_gs[i] = 0.f;
        }
        if (tid == 0) { d_hinge = 0.0; d_scon = 0.0; }
        return;
    }
    int w = (blockIdx.x * 256 + threadIdx.x) >> 5;
    int lane = threadIdx.x & 31;
    int t = w / 8192;
    int row = w - t * 8192;
    const float* src = (t == 0) ? x1 : (t == 1) ? x2 : (t == 2 || t == 4) ? x3 : x4;
    float2 v = ((const float2*)(src + (size_t)row * ND))[lane];
    if (t < 4) {
        float ss = v.x * v.x + v.y * v.y;
        #pragma unroll
        for (int o = 16; o; o >>= 1) ss += __shfl_xor_sync(0xFFFFFFFFu, ss, o);
        float sc = 1.0f / fmaxf(sqrtf(ss), 1e-12f);
        v.x *= sc; v.y *= sc;
    }
    __nv_bfloat16 hx = __float2bfloat16(v.x);
    __nv_bfloat16 hy = __float2bfloat16(v.y);
    size_t base = ((size_t)t * 8192 + row) * ND;
    ((__nv_bfloat162*)(d_hi + base))[lane] = __nv_bfloat162(hx, hy);
    if (t < 2) {
        __nv_bfloat16 lx = __float2bfloat16(v.x - __bfloat162float(hx));
        __nv_bfloat16 ly = __float2bfloat16(v.y - __bfloat162float(hy));
        ((__nv_bfloat162*)(d_lo + base))[lane] = __nv_bfloat162(lx, ly);
    }
}

// ================= mma.sync fused GEMM =================
// job 0: TL (2 passes: Ahi*Bhi + Ahi*Blo) store S + r + c
// job 1: TR (1 pass) r only;  job 2: BL (1 pass) c only;  job 3: hinge (1 pass)
#define SM_AHI  0
#define SM_BHI  16384
#define SM_BLO  32768
#define SM_RED  49152
#define SM_TOT  (49152 + 256)

__global__ void __launch_bounds__(256, 2) mma_gemm() {
    extern __shared__ char smem[];
    uint32_t sb = smem_u32(smem);
    int tid = threadIdx.x;
    int wid = tid >> 5;
    int lane = tid & 31;
    int warp_m = wid >> 2;
    int warp_n = wid & 3;
    int z = blockIdx.z;
    int b = z & 7;
    int job = z >> 3;
    int rowBase = blockIdx.y * 128;
    int colBase = blockIdx.x * 128;

    const int TA[4] = {0, 0, 2, 4};
    const int TB[4] = {1, 3, 1, 5};
    {
        size_t aoff = ((size_t)TA[job] * 8192 + b * NP + rowBase) * ND;
        size_t boff = ((size_t)TB[job] * 8192 + b * NP + colBase) * ND;
        const uint4* sA = (const uint4*)(d_hi + aoff);
        const uint4* sB = (const uint4*)(d_hi + boff);
        #pragma unroll
        for (int it = 0; it < 4; it++) {
            int idx = it * 256 + tid;
            int r = idx >> 3, c = idx & 7;
            uint32_t so = sw128(r * 128 + c * 16);
            *(uint4*)(smem + SM_AHI + so) = sA[idx];
            *(uint4*)(smem + SM_BHI + so) = sB[idx];
        }
        if (job == 0) {
            const uint4* sBl = (const uint4*)(d_lo + boff);
            #pragma unroll
            for (int it = 0; it < 4; it++) {
                int idx = it * 256 + tid;
                int r = idx >> 3, c = idx & 7;
                uint32_t so = sw128(r * 128 + c * 16);
                *(uint4*)(smem + SM_BLO + so) = sBl[idx];
            }
        }
    }
    __syncthreads();

    float acc[4][4][4];
    #pragma unroll
    for (int mi = 0; mi < 4; mi++)
        #pragma unroll
        for (int ni = 0; ni < 4; ni++)
            #pragma unroll
            for (int v = 0; v < 4; v++) acc[mi][ni][v] = 0.f;

    int mrow = warp_m * 64 + (lane & 15);
    int nrow = warp_n * 32 + (lane & 7);
    int l7 = lane & 7;

    #pragma unroll
    for (int k = 0; k < 4; k++) {
        uint32_t Af[4][4], Bh[4][2], Bl[4][2];
        int achunk = (2 * k + (lane >> 4)) ^ l7;
        int bchunk = (2 * k + ((lane >> 3) & 1)) ^ l7;
        #pragma unroll
        for (int mi = 0; mi < 4; mi++)
            ldsm_x4(Af[mi], sb + SM_AHI + (mrow + mi * 16) * 128 + achunk * 16);
        #pragma unroll
        for (int ni = 0; ni < 4; ni++)
            ldsm_x2(Bh[ni], sb + SM_BHI + (nrow + ni * 8) * 128 + bchunk * 16);
        #pragma unroll
        for (int mi = 0; mi < 4; mi++)
            #pragma unroll
            for (int ni = 0; ni < 4; ni++)
                mma_bf16(acc[mi][ni], Af[mi], Bh[ni]);           // hi*hi
        if (job == 0) {
            #pragma unroll
            for (int ni = 0; ni < 4; ni++)
                ldsm_x2(Bl[ni], sb + SM_BLO + (nrow + ni * 8) * 128 + bchunk * 16);
            #pragma unroll
            for (int mi = 0; mi < 4; mi++)
                #pragma unroll
                for (int ni = 0; ni < 4; ni++)
                    mma_bf16(acc[mi][ni], Af[mi], Bl[ni]);       // hi*lo
        }
    }

    int g = lane >> 2, t4 = lane & 3;

    if (job == 3) {
        float h = 0.f;
        #pragma unroll
        for (int mi = 0; mi < 4; mi++)
            #pragma unroll
            for (int ni = 0; ni < 4; ni++)
                #pragma unroll
                for (int v = 0; v < 4; v++)
                    h += fmaxf(MARGIN - acc[mi][ni][v], 0.f);
        #pragma unroll
        for (int o = 16; o; o >>= 1) h += __shfl_xor_sync(0xFFFFFFFFu, h, o);
        float* red = (float*)(smem + SM_RED);
        if (lane == 0) red[wid] = h;
        __syncthreads();
        if (tid == 0) {
            float s = 0.f;
            #pragma unroll
            for (int w = 0; w < 8; w++) s += red[w];
            atomicAdd(&d_hinge, (double)s);
        }
        return;
    }

    float rs[4][2], cs[4][2];
    #pragma unroll
    for (int i = 0; i < 4; i++) { rs[i][0] = rs[i][1] = cs[i][0] = cs[i][1] = 0.f; }

    #pragma unroll
    for (int mi = 0; mi < 4; mi++) {
        int row = rowBase + warp_m * 64 + mi * 16 + g;
        #pragma unroll
        for (int ni = 0; ni < 4; ni++) {
            float e0 = __expf(GAMMA * acc[mi][ni][0]);
            float e1 = __expf(GAMMA * acc[mi][ni][1]);
            float e2 = __expf(GAMMA * acc[mi][ni][2]);
            float e3 = __expf(GAMMA * acc[mi][ni][3]);
            if (job == 0) {
                int col = colBase + warp_n * 32 + ni * 8 + t4 * 2;
                float* Cp = d_C + ((size_t)b * NP + row) * NP + col;
                *(float2*)Cp = make_float2(e0, e1);
                *(float2*)(Cp + (size_t)8 * NP) = make_float2(e2, e3);
            }
            rs[mi][0] += e0 + e1;  rs[mi][1] += e2 + e3;
            cs[ni][0] += e0 + e2;  cs[ni][1] += e1 + e3;
        }
    }

    if (job <= 1) {
        #pragma unroll
        for (int mi = 0; mi < 4; mi++) {
            float r0 = rs[mi][0], r1 = rs[mi][1];
            r0 += __shfl_xor_sync(0xFFFFFFFFu, r0, 1);
            r0 += __shfl_xor_sync(0xFFFFFFFFu, r0, 2);
            r1 += __shfl_xor_sync(0xFFFFFFFFu, r1, 1);
            r1 += __shfl_xor_sync(0xFFFFFFFFu, r1, 2);
            if (t4 == 0) {
                int row = rowBase + warp_m * 64 + mi * 16 + g;
                atomicAdd(&d_r[b * NP + row], r0);
                atomicAdd(&d_r[b * NP + row + 8], r1);
            }
        }
    }
    if (job == 0 || job == 2) {
        #pragma unroll
        for (int ni = 0; ni < 4; ni++) {
            float c0 = cs[ni][0], c1 = cs[ni][1];
            c0 += __shfl_xor_sync(0xFFFFFFFFu, c0, 4);
            c0 += __shfl_xor_sync(0xFFFFFFFFu, c0, 8);
            c0 += __shfl_xor_sync(0xFFFFFFFFu, c0, 16);
            c1 += __shfl_xor_sync(0xFFFFFFFFu, c1, 4);
            c1 += __shfl_xor_sync(0xFFFFFFFFu, c1, 8);
            c1 += __shfl_xor_sync(0xFFFFFFFFu, c1, 16);
            if (lane < 4) {
                int col = colBase + warp_n * 32 + ni * 8 + lane * 2;
                atomicAdd(&d_c[b * NP + col], c0);
                atomicAdd(&d_c[b * NP + col + 1], c1);
            }
        }
    }
}

// ================= finalize: C -> u16 Cq/CTq + fused init sums (conflict-free u16 tile) ====
__global__ void finalize_kernel() {
    __shared__ unsigned short tile[64][74];
    __shared__ float scol[64];
    int b = blockIdx.z;
    int pBase = blockIdx.y * 64, qBase = blockIdx.x * 64;
    int tid = threadIdx.x;  // 256
    int lane = tid & 31;
    const float NK9 = -0.16029948f;   // -log2(e)/9
    float cpart[4] = {0.f, 0.f, 0.f, 0.f};
    float rpart[4];
    if (tid < 64) scol[tid] = 0.f;
    __syncthreads();
    #pragma unroll
    for (int v = 0; v < 4; v++) {
        int f4 = v * 256 + tid;
        int row = f4 >> 4;
        int c4 = f4 & 15;
        int p = pBase + row;
        size_t idx = ((size_t)b * NP + p) * NP + qBase + c4 * 4;
        float4 S = *(const float4*)(d_C + idx);
        float rp = d_r[b * NP + p];
        float4 cq = *(const float4*)(d_c + b * NP + qBase + c4 * 4);
        float4 C;
        C.x = 1.f - __fdividef(S.x, rp + cq.x - S.x);
        C.y = 1.f - __fdividef(S.y, rp + cq.y - S.y);
        C.z = 1.f - __fdividef(S.z, rp + cq.z - S.z);
        C.w = 1.f - __fdividef(S.w, rp + cq.w - S.w);
        ushort4 q = make_ushort4(quant(C.x), quant(C.y), quant(C.z), quant(C.w));
        *(ushort4*)(d_Cq + idx) = q;
        ((ushort2*)&tile[row][c4 * 4])[0] = make_ushort2(q.x, q.y);
        ((ushort2*)&tile[row][c4 * 4])[1] = make_ushort2(q.z, q.w);
        float e0 = exp2f(C.x * NK9);
        float e1 = exp2f(C.y * NK9);
        float e2 = exp2f(C.z * NK9);
        float e3 = exp2f(C.w * NK9);
        rpart[v] = (e0 + e1) + (e2 + e3);
        cpart[0] += e0; cpart[1] += e1; cpart[2] += e2; cpart[3] += e3;
    }
    #pragma unroll
    for (int v = 0; v < 4; v++) {
        float r = rpart[v];
        r += __shfl_xor_sync(0xFFFFFFFFu, r, 1);
        r += __shfl_xor_sync(0xFFFFFFFFu, r, 2);
        r += __shfl_xor_sync(0xFFFFFFFFu, r, 4);
        r += __shfl_xor_sync(0xFFFFFFFFu, r, 8);
        if ((lane & 15) == 0)
            atomicAdd(&d_fs[b * NP + pBase + v * 16 + (tid >> 4)], r);
    }
    #pragma unroll
    for (int j = 0; j < 4; j++) {
        cpart[j] += __shfl_xor_sync(0xFFFFFFFFu, cpart[j], 16);
        if (lane < 16) atomicAdd(&scol[lane * 4 + j], cpart[j]);
    }
    __syncthreads();
    if (tid < 64) atomicAdd(&d_gs[b * NP + qBase + tid], scol[tid]);

    int q = tid >> 2;
    int sbase = tid & 3;
    #pragma unroll
    for (int cc0 = 0; cc0 < 2; cc0++) {
        int cc = sbase + cc0 * 4;
        int p0 = cc * 8;
        unsigned short v16[8];
        #pragma unroll
        for (int i = 0; i < 8; i++) v16[i] = tile[p0 + i][q];
        uint4 o;
        o.x = (uint32_t)v16[0] | ((uint32_t)v16[1] << 16);
        o.y = (uint32_t)v16[2] | ((uint32_t)v16[3] << 16);
        o.z = (uint32_t)v16[4] | ((uint32_t)v16[5] << 16);
        o.w = (uint32_t)v16[6] | ((uint32_t)v16[7] << 16);
        *(uint4*)(d_CTq + ((size_t)b * NP + qBase + q) * NP + pBase + p0) = o;
    }
}

// ================= fused softmin: 4 rows/warp, 512 blocks = ONE wave =================
template <int INIT, int UMAX>
__global__ void __launch_bounds__(256, 4) softmin_kernel(int src, int dst, float eps, int mode) {
    __shared__ float hs[NP];
    __shared__ double blkred[8];
    int bx = blockIdx.x;          // 512 blocks
    int slice = bx >> 5;          // side*8 + b
    int side = slice >> 3;
    int b = slice & 7;
    int rowgrp = bx & 31;         // 32 groups of 32 rows
    int tid = threadIdx.x;
    int wid = tid >> 5, lane = tid & 31;

    float k2 = 1.4426950408889634f / eps;
    float qk = -IQSCALE * k2;
    const float* hsrc = (side == 0 ? (INIT ? d_gs : d_g[src])
                                   : (INIT ? d_fs : d_f[src])) + b * NP;
    for (int i = tid; i < NP; i += 256) {
        float h = hsrc[i];
        if (INIT) h = -9.0f * __logf(h);
        hs[i] = h * k2;
    }
    __syncthreads();

    int row0 = rowgrp * 32 + wid * 4;
    int idx0 = b * NP + row0;
    const unsigned short* Cb = (side == 0 ? d_Cq : d_CTq);
    const uint4* rp0 = (const uint4*)(Cb + ((size_t)b * NP + row0) * NP);   // row stride = 128 uint4
    const float4* h4 = (const float4*)hs;

    float mx[4] = {0.f, 0.f, 0.f, 0.f};
    if (UMAX) {
        float mm[4] = {-3.4e38f, -3.4e38f, -3.4e38f, -3.4e38f};
        #pragma unroll
        for (int jj = 0; jj < 4; jj++) {
            float4 h0 = h4[(jj * 32 + lane) * 2];
            float4 h1 = h4[(jj * 32 + lane) * 2 + 1];
            #pragma unroll
            for (int r = 0; r < 4; r++) {
                uint4 q = rp0[r * 128 + jj * 32 + lane];
                mm[r] = fmaxf(mm[r], fmaf((float)(q.x & 0xFFFF), qk, h0.x));
                mm[r] = fmaxf(mm[r], fmaf((float)(q.x >> 16),    qk, h0.y));
                mm[r] = fmaxf(mm[r], fmaf((float)(q.y & 0xFFFF), qk, h0.z));
                mm[r] = fmaxf(mm[r], fmaf((float)(q.y >> 16),    qk, h0.w));
                mm[r] = fmaxf(mm[r], fmaf((float)(q.z & 0xFFFF), qk, h1.x));
                mm[r] = fmaxf(mm[r], fmaf((float)(q.z >> 16),    qk, h1.y));
                mm[r] = fmaxf(mm[r], fmaf((float)(q.w & 0xFFFF), qk, h1.z));
                mm[r] = fmaxf(mm[r], fmaf((float)(q.w >> 16),    qk, h1.w));
            }
        }
        #pragma unroll
        for (int o = 16; o; o >>= 1) {
            #pragma unroll
            for (int r = 0; r < 4; r++)
                mm[r] = fmaxf(mm[r], __shfl_xor_sync(0xFFFFFFFFu, mm[r], o));
        }
        #pragma unroll
        for (int r = 0; r < 4; r++) mx[r] = mm[r];
    }

    float sa[4] = {0.f, 0.f, 0.f, 0.f}, sb[4] = {0.f, 0.f, 0.f, 0.f};
    #pragma unroll
    for (int jj = 0; jj < 4; jj++) {
        float4 h0 = h4[(jj * 32 + lane) * 2];
        float4 h1 = h4[(jj * 32 + lane) * 2 + 1];
        #pragma unroll
        for (int r = 0; r < 4; r++) {
            uint4 q = rp0[r * 128 + jj * 32 + lane];
            sa[r] += exp2f(fmaf((float)(q.x & 0xFFFF), qk, h0.x) - mx[r]);
            sb[r] += exp2f(fmaf((float)(q.x >> 16),    qk, h0.y) - mx[r]);
            sa[r] += exp2f(fmaf((float)(q.y & 0xFFFF), qk, h0.z) - mx[r]);
            sb[r] += exp2f(fmaf((float)(q.y >> 16),    qk, h0.w) - mx[r]);
            sa[r] += exp2f(fmaf((float)(q.z & 0xFFFF), qk, h1.x) - mx[r]);
            sb[r] += exp2f(fmaf((float)(q.z >> 16),    qk, h1.y) - mx[r]);
            sa[r] += exp2f(fmaf((float)(q.w & 0xFFFF), qk, h1.z) - mx[r]);
            sb[r] += exp2f(fmaf((float)(q.w >> 16),    qk, h1.w) - mx[r]);
        }
    }
    float sum[4];
    #pragma unroll
    for (int r = 0; r < 4; r++) sum[r] = sa[r] + sb[r];
    #pragma unroll
    for (int o = 16; o; o >>= 1) {
        #pragma unroll
        for (int r = 0; r < 4; r++)
            sum[r] += __shfl_xor_sync(0xFFFFFFFFu, sum[r], o);
    }

    const float ELN2 = 0.69314718055994531f;
    if (mode == 2) {
        if (lane == 0) {
            double acc = 0.0;
            #pragma unroll
            for (int r = 0; r < 4; r++)
                acc += (double)(-eps * ELN2 * (mx[r] + __log2f(sum[r])));
            blkred[wid] = acc;
        }
        __syncthreads();
        if (tid == 0) {
            double t = ((blkred[0] + blkred[1]) + (blkred[2] + blkred[3]))
                     + ((blkred[4] + blkred[5]) + (blkred[6] + blkred[7]));
            atomicAdd(&d_scon, t);
        }
    } else if (lane == 0) {
        float* pd = (side == 0 ? d_f[dst] : d_g[dst]);
        #pragma unroll
        for (int r = 0; r < 4; r++) {
            float val = -eps * ELN2 * (mx[r] + __log2f(sum[r]));
            float prev;
            if (INIT) prev = -9.0f * __logf((side == 0 ? d_fs : d_gs)[idx0 + r]);
            else      prev = (side == 0 ? d_f[src] : d_g[src])[idx0 + r];
            pd[idx0 + r] = 0.5f * (prev + val);
        }
    }
}

// ================= output =================
__global__ void write_out(float* out) {
    if (threadIdx.x == 0) {
        out[0] = (float)d_hinge;
        out[1] = (float)(d_scon / 8.0);
    }
}

// ================= launch =================
extern "C" void kernel_launch(void* const* d_in, const int* in_sizes, int n_in,
                              void* d_out, int out_size) {
    (void)in_sizes; (void)n_in; (void)out_size;
    const float* x1 = (const float*)d_in[0];
    const float* x2 = (const float*)d_in[1];
    const float* x3 = (const float*)d_in[2];
    const float* x4 = (const float*)d_in[3];
    float* out = (float*)d_out;

    double pexp = 2.0, diam = 3.0, blur = 0.05, scal = 0.5;
    float eps_list[16];
    int n_eps = 0;
    eps_list[n_eps++] = (float)pow(diam, pexp);
    for (double v = pexp * log(diam); v > pexp * log(blur); v += pexp * log(scal))
        eps_list[n_eps++] = (float)exp(v);
    eps_list[n_eps++] = (float)pow(blur, pexp);   // n_eps == 8

    cudaFuncSetAttribute(mma_gemm, cudaFuncAttributeMaxDynamicSharedMemorySize, SM_TOT);

    norm_split<<<6145, 256>>>(x1, x2, x3, x4);    // block 6144 = reset

    mma_gemm<<<dim3(8, 8, 32), 256, SM_TOT>>>();

    finalize_kernel<<<dim3(16, 16, NB), 256>>>(); // also produces init sums

    int cur = 0;
    for (int i = 0; i < n_eps; i++) {
        float eps = eps_list[i];
        bool um = (eps < 0.02f);
        if (i == 0)      softmin_kernel<1, 0><<<512, 256>>>(cur, 1 - cur, eps, 1);
        else if (!um)    softmin_kernel<0, 0><<<512, 256>>>(cur, 1 - cur, eps, 1);
        else             softmin_kernel<0, 1><<<512, 256>>>(cur, 1 - cur, eps, 1);
        cur = 1 - cur;
    }
    softmin_kernel<0, 1><<<512, 256>>>(cur, cur, eps_list[n_eps - 1], 2);

    write_out<<<1, 1>>>(out);
}

// round 14
// speedup vs baseline: 1.2071x; 1.2071x over previous
#include <cuda_runtime.h>
#include <cuda_bf16.h>
#include <math.h>
#include <stdint.h>

#define NB 8
#define NP 1024
#define ND 64
#define GAMMA 10.0f
#define MARGIN 0.1f
#define QSCALE 65535.0f
#define IQSCALE (1.0f / 65535.0f)

// ================= device scratch =================
__device__ __nv_bfloat16 d_hi[6 * NB * NP * ND];
__device__ __nv_bfloat16 d_lo[2 * NB * NP * ND];     // lo only for x1n, x2n
__device__ float d_C[NB * NP * NP];                  // sim S (32 MB), dead after finalize
__device__ unsigned short d_Cq[NB * NP * NP];        // u16 cost (16 MB)
__device__ unsigned short d_CTq[NB * NP * NP];       // u16 transposed cost (16 MB)
__device__ float d_r[NB * NP];
__device__ float d_c[NB * NP];
__device__ float d_fs[NB * NP];                      // init row sums  e^{-C/9}
__device__ float d_gs[NB * NP];                      // init col sums  e^{-C/9}
__device__ float d_f[2][NB * NP];
__device__ float d_g[2][NB * NP];
__device__ double d_hinge;
__device__ double d_scon;

// ================= helpers =================
__device__ __forceinline__ uint32_t smem_u32(const void* p) {
    uint32_t a;
    asm("{ .reg .u64 t; cvta.to.shared.u64 t, %1; cvt.u32.u64 %0, t; }" : "=r"(a) : "l"(p));
    return a;
}
__device__ __forceinline__ uint32_t sw128(uint32_t off) { return off ^ ((off >> 3) & 0x70); }

__device__ __forceinline__ void ldsm_x4(uint32_t* r, uint32_t addr) {
    asm volatile("ldmatrix.sync.aligned.m8n8.x4.shared.b16 {%0,%1,%2,%3}, [%4];"
        : "=r"(r[0]), "=r"(r[1]), "=r"(r[2]), "=r"(r[3]) : "r"(addr));
}
__device__ __forceinline__ void ldsm_x2(uint32_t* r, uint32_t addr) {
    asm volatile("ldmatrix.sync.aligned.m8n8.x2.shared.b16 {%0,%1}, [%2];"
        : "=r"(r[0]), "=r"(r[1]) : "r"(addr));
}
__device__ __forceinline__ void mma_bf16(float* d, const uint32_t* a, const uint32_t* b) {
    asm volatile("mma.sync.aligned.m16n8k16.row.col.f32.bf16.bf16.f32 "
        "{%0,%1,%2,%3}, {%4,%5,%6,%7}, {%8,%9}, {%0,%1,%2,%3};"
        : "+f"(d[0]), "+f"(d[1]), "+f"(d[2]), "+f"(d[3])
        : "r"(a[0]), "r"(a[1]), "r"(a[2]), "r"(a[3]), "r"(b[0]), "r"(b[1]));
}
__device__ __forceinline__ unsigned short quant(float v) {
    return (unsigned short)__float2uint_rn(fminf(fmaxf(v, 0.f), 1.f) * QSCALE);
}

// ================= normalize + hi/lo split (block 6144 = reset) =================
__global__ void norm_split(const float* __restrict__ x1, const float* __restrict__ x2,
                           const float* __restrict__ x3, const float* __restrict__ x4) {
    if (blockIdx.x == 6144) {
        int tid = threadIdx.x;
        for (int i = tid; i < NB * NP; i += 256) {
            d_r[i] = 0.f; d_c[i] = 0.f; d_fs[i] = 0.f; d_gs[i] = 0.f;
        }
        if (tid == 0) { d_hinge = 0.0; d_scon = 0.0; }
        return;
    }
    int w = (blockIdx.x * 256 + threadIdx.x) >> 5;
    int lane = threadIdx.x & 31;
    int t = w / 8192;
    int row = w - t * 8192;
    const float* src = (t == 0) ? x1 : (t == 1) ? x2 : (t == 2 || t == 4) ? x3 : x4;
    float2 v = ((const float2*)(src + (size_t)row * ND))[lane];
    if (t < 4) {
        float ss = v.x * v.x + v.y * v.y;
        #pragma unroll
        for (int o = 16; o; o >>= 1) ss += __shfl_xor_sync(0xFFFFFFFFu, ss, o);
        float sc = 1.0f / fmaxf(sqrtf(ss), 1e-12f);
        v.x *= sc; v.y *= sc;
    }
    __nv_bfloat16 hx = __float2bfloat16(v.x);
    __nv_bfloat16 hy = __float2bfloat16(v.y);
    size_t base = ((size_t)t * 8192 + row) * ND;
    ((__nv_bfloat162*)(d_hi + base))[lane] = __nv_bfloat162(hx, hy);
    if (t < 2) {
        __nv_bfloat16 lx = __float2bfloat16(v.x - __bfloat162float(hx));
        __nv_bfloat16 ly = __float2bfloat16(v.y - __bfloat162float(hy));
        ((__nv_bfloat162*)(d_lo + base))[lane] = __nv_bfloat162(lx, ly);
    }
}

// ================= mma.sync fused GEMM =================
// job 0: TL (2 passes: Ahi*Bhi + Ahi*Blo) store S + r + c
// job 1: TR (1 pass) r only;  job 2: BL (1 pass) c only;  job 3: hinge (1 pass)
#define SM_AHI  0
#define SM_BHI  16384
#define SM_BLO  32768
#define SM_RED  49152
#define SM_TOT  (49152 + 256)

__global__ void __launch_bounds__(256, 2) mma_gemm() {
    extern __shared__ char smem[];
    uint32_t sb = smem_u32(smem);
    int tid = threadIdx.x;
    int wid = tid >> 5;
    int lane = tid & 31;
    int warp_m = wid >> 2;
    int warp_n = wid & 3;
    int z = blockIdx.z;
    int b = z & 7;
    int job = z >> 3;
    int rowBase = blockIdx.y * 128;
    int colBase = blockIdx.x * 128;

    const int TA[4] = {0, 0, 2, 4};
    const int TB[4] = {1, 3, 1, 5};
    {
        size_t aoff = ((size_t)TA[job] * 8192 + b * NP + rowBase) * ND;
        size_t boff = ((size_t)TB[job] * 8192 + b * NP + colBase) * ND;
        const uint4* sA = (const uint4*)(d_hi + aoff);
        const uint4* sB = (const uint4*)(d_hi + boff);
        #pragma unroll
        for (int it = 0; it < 4; it++) {
            int idx = it * 256 + tid;
            int r = idx >> 3, c = idx & 7;
            uint32_t so = sw128(r * 128 + c * 16);
            *(uint4*)(smem + SM_AHI + so) = sA[idx];
            *(uint4*)(smem + SM_BHI + so) = sB[idx];
        }
        if (job == 0) {
            const uint4* sBl = (const uint4*)(d_lo + boff);
            #pragma unroll
            for (int it = 0; it < 4; it++) {
                int idx = it * 256 + tid;
                int r = idx >> 3, c = idx & 7;
                uint32_t so = sw128(r * 128 + c * 16);
                *(uint4*)(smem + SM_BLO + so) = sBl[idx];
            }
        }
    }
    __syncthreads();

    float acc[4][4][4];
    #pragma unroll
    for (int mi = 0; mi < 4; mi++)
        #pragma unroll
        for (int ni = 0; ni < 4; ni++)
            #pragma unroll
            for (int v = 0; v < 4; v++) acc[mi][ni][v] = 0.f;

    int mrow = warp_m * 64 + (lane & 15);
    int nrow = warp_n * 32 + (lane & 7);
    int l7 = lane & 7;

    #pragma unroll
    for (int k = 0; k < 4; k++) {
        uint32_t Af[4][4], Bh[4][2], Bl[4][2];
        int achunk = (2 * k + (lane >> 4)) ^ l7;
        int bchunk = (2 * k + ((lane >> 3) & 1)) ^ l7;
        #pragma unroll
        for (int mi = 0; mi < 4; mi++)
            ldsm_x4(Af[mi], sb + SM_AHI + (mrow + mi * 16) * 128 + achunk * 16);
        #pragma unroll
        for (int ni = 0; ni < 4; ni++)
            ldsm_x2(Bh[ni], sb + SM_BHI + (nrow + ni * 8) * 128 + bchunk * 16);
        #pragma unroll
        for (int mi = 0; mi < 4; mi++)
            #pragma unroll
            for (int ni = 0; ni < 4; ni++)
                mma_bf16(acc[mi][ni], Af[mi], Bh[ni]);           // hi*hi
        if (job == 0) {
            #pragma unroll
            for (int ni = 0; ni < 4; ni++)
                ldsm_x2(Bl[ni], sb + SM_BLO + (nrow + ni * 8) * 128 + bchunk * 16);
            #pragma unroll
            for (int mi = 0; mi < 4; mi++)
                #pragma unroll
                for (int ni = 0; ni < 4; ni++)
                    mma_bf16(acc[mi][ni], Af[mi], Bl[ni]);       // hi*lo
        }
    }

    int g = lane >> 2, t4 = lane & 3;

    if (job == 3) {
        float h = 0.f;
        #pragma unroll
        for (int mi = 0; mi < 4; mi++)
            #pragma unroll
            for (int ni = 0; ni < 4; ni++)
                #pragma unroll
                for (int v = 0; v < 4; v++)
                    h += fmaxf(MARGIN - acc[mi][ni][v], 0.f);
        #pragma unroll
        for (int o = 16; o; o >>= 1) h += __shfl_xor_sync(0xFFFFFFFFu, h, o);
        float* red = (float*)(smem + SM_RED);
        if (lane == 0) red[wid] = h;
        __syncthreads();
        if (tid == 0) {
            float s = 0.f;
            #pragma unroll
            for (int w = 0; w < 8; w++) s += red[w];
            atomicAdd(&d_hinge, (double)s);
        }
        return;
    }

    float rs[4][2], cs[4][2];
    #pragma unroll
    for (int i = 0; i < 4; i++) { rs[i][0] = rs[i][1] = cs[i][0] = cs[i][1] = 0.f; }

    #pragma unroll
    for (int mi = 0; mi < 4; mi++) {
        int row = rowBase + warp_m * 64 + mi * 16 + g;
        #pragma unroll
        for (int ni = 0; ni < 4; ni++) {
            float e0 = __expf(GAMMA * acc[mi][ni][0]);
            float e1 = __expf(GAMMA * acc[mi][ni][1]);
            float e2 = __expf(GAMMA * acc[mi][ni][2]);
            float e3 = __expf(GAMMA * acc[mi][ni][3]);
            if (job == 0) {
                int col = colBase + warp_n * 32 + ni * 8 + t4 * 2;
                float* Cp = d_C + ((size_t)b * NP + row) * NP + col;
                *(float2*)Cp = make_float2(e0, e1);
                *(float2*)(Cp + (size_t)8 * NP) = make_float2(e2, e3);
            }
            rs[mi][0] += e0 + e1;  rs[mi][1] += e2 + e3;
            cs[ni][0] += e0 + e2;  cs[ni][1] += e1 + e3;
        }
    }

    if (job <= 1) {
        #pragma unroll
        for (int mi = 0; mi < 4; mi++) {
            float r0 = rs[mi][0], r1 = rs[mi][1];
            r0 += __shfl_xor_sync(0xFFFFFFFFu, r0, 1);
            r0 += __shfl_xor_sync(0xFFFFFFFFu, r0, 2);
            r1 += __shfl_xor_sync(0xFFFFFFFFu, r1, 1);
            r1 += __shfl_xor_sync(0xFFFFFFFFu, r1, 2);
            if (t4 == 0) {
                int row = rowBase + warp_m * 64 + mi * 16 + g;
                atomicAdd(&d_r[b * NP + row], r0);
                atomicAdd(&d_r[b * NP + row + 8], r1);
            }
        }
    }
    if (job == 0 || job == 2) {
        #pragma unroll
        for (int ni = 0; ni < 4; ni++) {
            float c0 = cs[ni][0], c1 = cs[ni][1];
            c0 += __shfl_xor_sync(0xFFFFFFFFu, c0, 4);
            c0 += __shfl_xor_sync(0xFFFFFFFFu, c0, 8);
            c0 += __shfl_xor_sync(0xFFFFFFFFu, c0, 16);
            c1 += __shfl_xor_sync(0xFFFFFFFFu, c1, 4);
            c1 += __shfl_xor_sync(0xFFFFFFFFu, c1, 8);
            c1 += __shfl_xor_sync(0xFFFFFFFFu, c1, 16);
            if (lane < 4) {
                int col = colBase + warp_n * 32 + ni * 8 + lane * 2;
                atomicAdd(&d_c[b * NP + col], c0);
                atomicAdd(&d_c[b * NP + col + 1], c1);
            }
        }
    }
}

// ================= finalize: C -> u16 Cq/CTq + fused init sums (conflict-free u16 tile) ====
__global__ void finalize_kernel() {
    __shared__ unsigned short tile[64][74];
    __shared__ float scol[64];
    int b = blockIdx.z;
    int pBase = blockIdx.y * 64, qBase = blockIdx.x * 64;
    int tid = threadIdx.x;  // 256
    int lane = tid & 31;
    const float NK9 = -0.16029948f;   // -log2(e)/9
    float cpart[4] = {0.f, 0.f, 0.f, 0.f};
    float rpart[4];
    if (tid < 64) scol[tid] = 0.f;
    __syncthreads();
    #pragma unroll
    for (int v = 0; v < 4; v++) {
        int f4 = v * 256 + tid;
        int row = f4 >> 4;
        int c4 = f4 & 15;
        int p = pBase + row;
        size_t idx = ((size_t)b * NP + p) * NP + qBase + c4 * 4;
        float4 S = *(const float4*)(d_C + idx);
        float rp = d_r[b * NP + p];
        float4 cq = *(const float4*)(d_c + b * NP + qBase + c4 * 4);
        float4 C;
        C.x = 1.f - __fdividef(S.x, rp + cq.x - S.x);
        C.y = 1.f - __fdividef(S.y, rp + cq.y - S.y);
        C.z = 1.f - __fdividef(S.z, rp + cq.z - S.z);
        C.w = 1.f - __fdividef(S.w, rp + cq.w - S.w);
        ushort4 q = make_ushort4(quant(C.x), quant(C.y), quant(C.z), quant(C.w));
        *(ushort4*)(d_Cq + idx) = q;
        ((ushort2*)&tile[row][c4 * 4])[0] = make_ushort2(q.x, q.y);
        ((ushort2*)&tile[row][c4 * 4])[1] = make_ushort2(q.z, q.w);
        float e0 = exp2f(C.x * NK9);
        float e1 = exp2f(C.y * NK9);
        float e2 = exp2f(C.z * NK9);
        float e3 = exp2f(C.w * NK9);
        rpart[v] = (e0 + e1) + (e2 + e3);
        cpart[0] += e0; cpart[1] += e1; cpart[2] += e2; cpart[3] += e3;
    }
    #pragma unroll
    for (int v = 0; v < 4; v++) {
        float r = rpart[v];
        r += __shfl_xor_sync(0xFFFFFFFFu, r, 1);
        r += __shfl_xor_sync(0xFFFFFFFFu, r, 2);
        r += __shfl_xor_sync(0xFFFFFFFFu, r, 4);
        r += __shfl_xor_sync(0xFFFFFFFFu, r, 8);
        if ((lane & 15) == 0)
            atomicAdd(&d_fs[b * NP + pBase + v * 16 + (tid >> 4)], r);
    }
    #pragma unroll
    for (int j = 0; j < 4; j++) {
        cpart[j] += __shfl_xor_sync(0xFFFFFFFFu, cpart[j], 16);
        if (lane < 16) atomicAdd(&scol[lane * 4 + j], cpart[j]);
    }
    __syncthreads();
    if (tid < 64) atomicAdd(&d_gs[b * NP + qBase + tid], scol[tid]);

    int q = tid >> 2;
    int sbase = tid & 3;
    #pragma unroll
    for (int cc0 = 0; cc0 < 2; cc0++) {
        int cc = sbase + cc0 * 4;
        int p0 = cc * 8;
        unsigned short v16[8];
        #pragma unroll
        for (int i = 0; i < 8; i++) v16[i] = tile[p0 + i][q];
        uint4 o;
        o.x = (uint32_t)v16[0] | ((uint32_t)v16[1] << 16);
        o.y = (uint32_t)v16[2] | ((uint32_t)v16[3] << 16);
        o.z = (uint32_t)v16[4] | ((uint32_t)v16[5] << 16);
        o.w = (uint32_t)v16[6] | ((uint32_t)v16[7] << 16);
        *(uint4*)(d_CTq + ((size_t)b * NP + qBase + q) * NP + pBase + p0) = o;
    }
}

// ================= fused softmin: 2 rows/warp, h cached in smem =================
// UMAX=1 uses single-pass ONLINE logsumexp (no second row read)
template <int INIT, int UMAX>
__global__ void softmin_kernel(int src, int dst, float eps, int mode) {
    __shared__ float hs[NP];
    __shared__ double blkred[8];
    int bx = blockIdx.x;          // 1024 blocks
    int slice = bx >> 6;
    int side = slice >> 3;
    int b = slice & 7;
    int rowgrp = bx & 63;
    int tid = threadIdx.x;
    int wid = tid >> 5, lane = tid & 31;

    float k2 = 1.4426950408889634f / eps;
    float qk = -IQSCALE * k2;
    const float* hsrc = (side == 0 ? (INIT ? d_gs : d_g[src])
                                   : (INIT ? d_fs : d_f[src])) + b * NP;
    for (int i = tid; i < NP; i += 256) {
        float h = hsrc[i];
        if (INIT) h = -9.0f * __logf(h);
        hs[i] = h * k2;
    }
    __syncthreads();

    int row0 = rowgrp * 16 + wid * 2;
    int idxA = b * NP + row0;
    const unsigned short* Cb = (side == 0 ? d_Cq : d_CTq);
    const uint4* rA = (const uint4*)(Cb + ((size_t)b * NP + row0) * NP);
    const uint4* rB = (const uint4*)(Cb + ((size_t)b * NP + row0 + 1) * NP);
    const float4* h4 = (const float4*)hs;

    float mA = 0.f, mB = 0.f;        // running maxima (0 when !UMAX)
    float sA0 = 0, sA1 = 0, sB0 = 0, sB1 = 0;
    if (UMAX) { mA = -3.4e38f; mB = -3.4e38f; }

    #pragma unroll
    for (int jj = 0; jj < 4; jj++) {
        uint4 qa = rA[jj * 32 + lane];
        uint4 qb = rB[jj * 32 + lane];
        float4 h0 = h4[(jj * 32 + lane) * 2];
        float4 h1 = h4[(jj * 32 + lane) * 2 + 1];
        float tA[8], tB[8];
        tA[0] = fmaf((float)(qa.x & 0xFFFF), qk, h0.x);
        tB[0] = fmaf((float)(qb.x & 0xFFFF), qk, h0.x);
        tA[1] = fmaf((float)(qa.x >> 16),    qk, h0.y);
        tB[1] = fmaf((float)(qb.x >> 16),    qk, h0.y);
        tA[2] = fmaf((float)(qa.y & 0xFFFF), qk, h0.z);
        tB[2] = fmaf((float)(qb.y & 0xFFFF), qk, h0.z);
        tA[3] = fmaf((float)(qa.y >> 16),    qk, h0.w);
        tB[3] = fmaf((float)(qb.y >> 16),    qk, h0.w);
        tA[4] = fmaf((float)(qa.z & 0xFFFF), qk, h1.x);
        tB[4] = fmaf((float)(qb.z & 0xFFFF), qk, h1.x);
        tA[5] = fmaf((float)(qa.z >> 16),    qk, h1.y);
        tB[5] = fmaf((float)(qb.z >> 16),    qk, h1.y);
        tA[6] = fmaf((float)(qa.w & 0xFFFF), qk, h1.z);
        tB[6] = fmaf((float)(qb.w & 0xFFFF), qk, h1.z);
        tA[7] = fmaf((float)(qa.w >> 16),    qk, h1.w);
        tB[7] = fmaf((float)(qb.w >> 16),    qk, h1.w);
        if (UMAX) {
            float lA = fmaxf(fmaxf(fmaxf(tA[0], tA[1]), fmaxf(tA[2], tA[3])),
                             fmaxf(fmaxf(tA[4], tA[5]), fmaxf(tA[6], tA[7])));
            float lB = fmaxf(fmaxf(fmaxf(tB[0], tB[1]), fmaxf(tB[2], tB[3])),
                             fmaxf(fmaxf(tB[4], tB[5]), fmaxf(tB[6], tB[7])));
            float nA = fmaxf(mA, lA);
            float nB = fmaxf(mB, lB);
            float scA = exp2f(mA - nA);     // ==1 when unchanged; ==0 from -inf
            float scB = exp2f(mB - nB);
            sA0 *= scA; sA1 *= scA;
            sB0 *= scB; sB1 *= scB;
            mA = nA; mB = nB;
        }
        sA0 += exp2f(tA[0] - mA) + exp2f(tA[2] - mA) + exp2f(tA[4] - mA) + exp2f(tA[6] - mA);
        sA1 += exp2f(tA[1] - mA) + exp2f(tA[3] - mA) + exp2f(tA[5] - mA) + exp2f(tA[7] - mA);
        sB0 += exp2f(tB[0] - mB) + exp2f(tB[2] - mB) + exp2f(tB[4] - mB) + exp2f(tB[6] - mB);
        sB1 += exp2f(tB[1] - mB) + exp2f(tB[3] - mB) + exp2f(tB[5] - mB) + exp2f(tB[7] - mB);
    }
    float sumA = sA0 + sA1;
    float sumB = sB0 + sB1;

    if (UMAX) {
        // cross-lane (m, s) merge
        #pragma unroll
        for (int o = 16; o; o >>= 1) {
            float moA = __shfl_xor_sync(0xFFFFFFFFu, mA, o);
            float soA = __shfl_xor_sync(0xFFFFFFFFu, sumA, o);
            float moB = __shfl_xor_sync(0xFFFFFFFFu, mB, o);
            float soB = __shfl_xor_sync(0xFFFFFFFFu, sumB, o);
            float nA = fmaxf(mA, moA);
            float nB = fmaxf(mB, moB);
            sumA = sumA * exp2f(mA - nA) + soA * exp2f(moA - nA);
            sumB = sumB * exp2f(mB - nB) + soB * exp2f(moB - nB);
            mA = nA; mB = nB;
        }
    } else {
        #pragma unroll
        for (int o = 16; o; o >>= 1) {
            sumA += __shfl_xor_sync(0xFFFFFFFFu, sumA, o);
            sumB += __shfl_xor_sync(0xFFFFFFFFu, sumB, o);
        }
    }

    const float ELN2 = 0.69314718055994531f;
    if (mode == 2) {
        if (lane == 0) {
            float vA = -eps * ELN2 * (mA + __log2f(sumA));
            float vB = -eps * ELN2 * (mB + __log2f(sumB));
            blkred[wid] = (double)(vA + vB);
        }
        __syncthreads();
        if (tid == 0) {
            double t = ((blkred[0] + blkred[1]) + (blkred[2] + blkred[3]))
                     + ((blkred[4] + blkred[5]) + (blkred[6] + blkred[7]));
            atomicAdd(&d_scon, t);
        }
    } else if (lane == 0) {
        float vA = -eps * ELN2 * (mA + __log2f(sumA));
        float vB = -eps * ELN2 * (mB + __log2f(sumB));
        float pA, pB;
        if (INIT) {
            const float* ps = (side == 0 ? d_fs : d_gs);
            pA = -9.0f * __logf(ps[idxA]);
            pB = -9.0f * __logf(ps[idxA + 1]);
        } else {
            const float* ps = (side == 0 ? d_f[src] : d_g[src]);
            pA = ps[idxA];
            pB = ps[idxA + 1];
        }
        float* pd = (side == 0 ? d_f[dst] : d_g[dst]);
        pd[idxA]     = 0.5f * (pA + vA);
        pd[idxA + 1] = 0.5f * (pB + vB);
    }
}

// ================= output =================
__global__ void write_out(float* out) {
    if (threadIdx.x == 0) {
        out[0] = (float)d_hinge;
        out[1] = (float)(d_scon / 8.0);
    }
}

// ================= launch =================
extern "C" void kernel_launch(void* const* d_in, const int* in_sizes, int n_in,
                              void* d_out, int out_size) {
    (void)in_sizes; (void)n_in; (void)out_size;
    const float* x1 = (const float*)d_in[0];
    const float* x2 = (const float*)d_in[1];
    const float* x3 = (const float*)d_in[2];
    const float* x4 = (const float*)d_in[3];
    float* out = (float*)d_out;

    double pexp = 2.0, diam = 3.0, blur = 0.05, scal = 0.5;
    float eps_list[16];
    int n_eps = 0;
    eps_list[n_eps++] = (float)pow(diam, pexp);
    for (double v = pexp * log(diam); v > pexp * log(blur); v += pexp * log(scal))
        eps_list[n_eps++] = (float)exp(v);
    eps_list[n_eps++] = (float)pow(blur, pexp);   // n_eps == 8

    cudaFuncSetAttribute(mma_gemm, cudaFuncAttributeMaxDynamicSharedMemorySize, SM_TOT);

    norm_split<<<6145, 256>>>(x1, x2, x3, x4);    // block 6144 = reset

    mma_gemm<<<dim3(8, 8, 32), 256, SM_TOT>>>();

    finalize_kernel<<<dim3(16, 16, NB), 256>>>(); // also produces init sums

    int cur = 0;
    for (int i = 0; i < n_eps; i++) {
        float eps = eps_list[i];
        bool um = (eps < 0.02f);
        if (i == 0)      softmin_kernel<1, 0><<<1024, 256>>>(cur, 1 - cur, eps, 1);
        else if (!um)    softmin_kernel<0, 0><<<1024, 256>>>(cur, 1 - cur, eps, 1);
        else             softmin_kernel<0, 1><<<1024, 256>>>(cur, 1 - cur, eps, 1);
        cur = 1 - cur;
    }
    softmin_kernel<0, 1><<<1024, 256>>>(cur, cur, eps_list[n_eps - 1], 2);

    write_out<<<1, 1>>>(out);
}

// round 15
// speedup vs baseline: 1.2303x; 1.0192x over previous
#include <cuda_runtime.h>
#include <cuda_bf16.h>
#include <cuda_fp16.h>
#include <math.h>
#include <stdint.h>

#define NB 8
#define NP 1024
#define ND 64
#define GAMMA 10.0f
#define MARGIN 0.1f
#define QSCALE 65535.0f
#define IQSCALE (1.0f / 65535.0f)

// ================= device scratch =================
__device__ __nv_bfloat16 d_hi[6 * NB * NP * ND];
__device__ __nv_bfloat16 d_lo[2 * NB * NP * ND];     // lo only for x1n, x2n
__device__ __half d_Sh[NB * NP * NP];                // sim S fp16 (16 MB), dead after finalize
__device__ unsigned short d_Cq[NB * NP * NP];        // u16 cost (16 MB)
__device__ unsigned short d_CTq[NB * NP * NP];       // u16 transposed cost (16 MB)
__device__ float d_r[NB * NP];
__device__ float d_c[NB * NP];
__device__ float d_fs[NB * NP];                      // init row sums  e^{-C/9}
__device__ float d_gs[NB * NP];                      // init col sums  e^{-C/9}
__device__ float d_f[2][NB * NP];
__device__ float d_g[2][NB * NP];
__device__ double d_hinge;
__device__ double d_scon;

// ================= helpers =================
__device__ __forceinline__ uint32_t smem_u32(const void* p) {
    uint32_t a;
    asm("{ .reg .u64 t; cvta.to.shared.u64 t, %1; cvt.u32.u64 %0, t; }" : "=r"(a) : "l"(p));
    return a;
}
__device__ __forceinline__ uint32_t sw128(uint32_t off) { return off ^ ((off >> 3) & 0x70); }

__device__ __forceinline__ void ldsm_x4(uint32_t* r, uint32_t addr) {
    asm volatile("ldmatrix.sync.aligned.m8n8.x4.shared.b16 {%0,%1,%2,%3}, [%4];"
        : "=r"(r[0]), "=r"(r[1]), "=r"(r[2]), "=r"(r[3]) : "r"(addr));
}
__device__ __forceinline__ void ldsm_x2(uint32_t* r, uint32_t addr) {
    asm volatile("ldmatrix.sync.aligned.m8n8.x2.shared.b16 {%0,%1}, [%2];"
        : "=r"(r[0]), "=r"(r[1]) : "r"(addr));
}
__device__ __forceinline__ void mma_bf16(float* d, const uint32_t* a, const uint32_t* b) {
    asm volatile("mma.sync.aligned.m16n8k16.row.col.f32.bf16.bf16.f32 "
        "{%0,%1,%2,%3}, {%4,%5,%6,%7}, {%8,%9}, {%0,%1,%2,%3};"
        : "+f"(d[0]), "+f"(d[1]), "+f"(d[2]), "+f"(d[3])
        : "r"(a[0]), "r"(a[1]), "r"(a[2]), "r"(a[3]), "r"(b[0]), "r"(b[1]));
}
__device__ __forceinline__ unsigned short quant(float v) {
    return (unsigned short)__float2uint_rn(fminf(fmaxf(v, 0.f), 1.f) * QSCALE);
}

// ================= normalize + hi/lo split (block 6144 = reset) =================
__global__ void norm_split(const float* __restrict__ x1, const float* __restrict__ x2,
                           const float* __restrict__ x3, const float* __restrict__ x4) {
    if (blockIdx.x == 6144) {
        int tid = threadIdx.x;
        for (int i = tid; i < NB * NP; i += 256) {
            d_r[i] = 0.f; d_c[i] = 0.f; d_fs[i] = 0.f; d_gs[i] = 0.f;
        }
        if (tid == 0) { d_hinge = 0.0; d_scon = 0.0; }
        return;
    }
    int w = (blockIdx.x * 256 + threadIdx.x) >> 5;
    int lane = threadIdx.x & 31;
    int t = w / 8192;
    int row = w - t * 8192;
    const float* src = (t == 0) ? x1 : (t == 1) ? x2 : (t == 2 || t == 4) ? x3 : x4;
    float2 v = ((const float2*)(src + (size_t)row * ND))[lane];
    if (t < 4) {
        float ss = v.x * v.x + v.y * v.y;
        #pragma unroll
        for (int o = 16; o; o >>= 1) ss += __shfl_xor_sync(0xFFFFFFFFu, ss, o);
        float sc = 1.0f / fmaxf(sqrtf(ss), 1e-12f);
        v.x *= sc; v.y *= sc;
    }
    __nv_bfloat16 hx = __float2bfloat16(v.x);
    __nv_bfloat16 hy = __float2bfloat16(v.y);
    size_t base = ((size_t)t * 8192 + row) * ND;
    ((__nv_bfloat162*)(d_hi + base))[lane] = __nv_bfloat162(hx, hy);
    if (t < 2) {
        __nv_bfloat16 lx = __float2bfloat16(v.x - __bfloat162float(hx));
        __nv_bfloat16 ly = __float2bfloat16(v.y - __bfloat162float(hy));
        ((__nv_bfloat162*)(d_lo + base))[lane] = __nv_bfloat162(lx, ly);
    }
}

// ================= mma.sync fused GEMM =================
// job 0: TL (2 passes: Ahi*Bhi + Ahi*Blo) store S (fp16) + r + c
// job 1: TR (1 pass) r only;  job 2: BL (1 pass) c only;  job 3: hinge (1 pass)
#define SM_AHI  0
#define SM_BHI  16384
#define SM_BLO  32768
#define SM_RED  49152
#define SM_TOT  (49152 + 256)

__global__ void __launch_bounds__(256, 2) mma_gemm() {
    extern __shared__ char smem[];
    uint32_t sb = smem_u32(smem);
    int tid = threadIdx.x;
    int wid = tid >> 5;
    int lane = tid & 31;
    int warp_m = wid >> 2;
    int warp_n = wid & 3;
    int z = blockIdx.z;
    int b = z & 7;
    int job = z >> 3;
    int rowBase = blockIdx.y * 128;
    int colBase = blockIdx.x * 128;

    const int TA[4] = {0, 0, 2, 4};
    const int TB[4] = {1, 3, 1, 5};
    {
        size_t aoff = ((size_t)TA[job] * 8192 + b * NP + rowBase) * ND;
        size_t boff = ((size_t)TB[job] * 8192 + b * NP + colBase) * ND;
        const uint4* sA = (const uint4*)(d_hi + aoff);
        const uint4* sB = (const uint4*)(d_hi + boff);
        #pragma unroll
        for (int it = 0; it < 4; it++) {
            int idx = it * 256 + tid;
            int r = idx >> 3, c = idx & 7;
            uint32_t so = sw128(r * 128 + c * 16);
            *(uint4*)(smem + SM_AHI + so) = sA[idx];
            *(uint4*)(smem + SM_BHI + so) = sB[idx];
        }
        if (job == 0) {
            const uint4* sBl = (const uint4*)(d_lo + boff);
            #pragma unroll
            for (int it = 0; it < 4; it++) {
                int idx = it * 256 + tid;
                int r = idx >> 3, c = idx & 7;
                uint32_t so = sw128(r * 128 + c * 16);
                *(uint4*)(smem + SM_BLO + so) = sBl[idx];
            }
        }
    }
    __syncthreads();

    float acc[4][4][4];
    #pragma unroll
    for (int mi = 0; mi < 4; mi++)
        #pragma unroll
        for (int ni = 0; ni < 4; ni++)
            #pragma unroll
            for (int v = 0; v < 4; v++) acc[mi][ni][v] = 0.f;

    int mrow = warp_m * 64 + (lane & 15);
    int nrow = warp_n * 32 + (lane & 7);
    int l7 = lane & 7;

    #pragma unroll
    for (int k = 0; k < 4; k++) {
        uint32_t Af[4][4], Bh[4][2], Bl[4][2];
        int achunk = (2 * k + (lane >> 4)) ^ l7;
        int bchunk = (2 * k + ((lane >> 3) & 1)) ^ l7;
        #pragma unroll
        for (int mi = 0; mi < 4; mi++)
            ldsm_x4(Af[mi], sb + SM_AHI + (mrow + mi * 16) * 128 + achunk * 16);
        #pragma unroll
        for (int ni = 0; ni < 4; ni++)
            ldsm_x2(Bh[ni], sb + SM_BHI + (nrow + ni * 8) * 128 + bchunk * 16);
        #pragma unroll
        for (int mi = 0; mi < 4; mi++)
            #pragma unroll
            for (int ni = 0; ni < 4; ni++)
                mma_bf16(acc[mi][ni], Af[mi], Bh[ni]);           // hi*hi
        if (job == 0) {
            #pragma unroll
            for (int ni = 0; ni < 4; ni++)
                ldsm_x2(Bl[ni], sb + SM_BLO + (nrow + ni * 8) * 128 + bchunk * 16);
            #pragma unroll
            for (int mi = 0; mi < 4; mi++)
                #pragma unroll
                for (int ni = 0; ni < 4; ni++)
                    mma_bf16(acc[mi][ni], Af[mi], Bl[ni]);       // hi*lo
        }
    }

    int g = lane >> 2, t4 = lane & 3;

    if (job == 3) {
        float h = 0.f;
        #pragma unroll
        for (int mi = 0; mi < 4; mi++)
            #pragma unroll
            for (int ni = 0; ni < 4; ni++)
                #pragma unroll
                for (int v = 0; v < 4; v++)
                    h += fmaxf(MARGIN - acc[mi][ni][v], 0.f);
        #pragma unroll
        for (int o = 16; o; o >>= 1) h += __shfl_xor_sync(0xFFFFFFFFu, h, o);
        float* red = (float*)(smem + SM_RED);
        if (lane == 0) red[wid] = h;
        __syncthreads();
        if (tid == 0) {
            float s = 0.f;
            #pragma unroll
            for (int w = 0; w < 8; w++) s += red[w];
            atomicAdd(&d_hinge, (double)s);
        }
        return;
    }

    float rs[4][2], cs[4][2];
    #pragma unroll
    for (int i = 0; i < 4; i++) { rs[i][0] = rs[i][1] = cs[i][0] = cs[i][1] = 0.f; }

    #pragma unroll
    for (int mi = 0; mi < 4; mi++) {
        int row = rowBase + warp_m * 64 + mi * 16 + g;
        #pragma unroll
        for (int ni = 0; ni < 4; ni++) {
            float e0 = __expf(GAMMA * acc[mi][ni][0]);
            float e1 = __expf(GAMMA * acc[mi][ni][1]);
            float e2 = __expf(GAMMA * acc[mi][ni][2]);
            float e3 = __expf(GAMMA * acc[mi][ni][3]);
            if (job == 0) {
                int col = colBase + warp_n * 32 + ni * 8 + t4 * 2;
                __half* Sp = d_Sh + ((size_t)b * NP + row) * NP + col;
                *(__half2*)Sp = __floats2half2_rn(e0, e1);
                *(__half2*)(Sp + (size_t)8 * NP) = __floats2half2_rn(e2, e3);
            }
            rs[mi][0] += e0 + e1;  rs[mi][1] += e2 + e3;
            cs[ni][0] += e0 + e2;  cs[ni][1] += e1 + e3;
        }
    }

    if (job <= 1) {
        #pragma unroll
        for (int mi = 0; mi < 4; mi++) {
            float r0 = rs[mi][0], r1 = rs[mi][1];
            r0 += __shfl_xor_sync(0xFFFFFFFFu, r0, 1);
            r0 += __shfl_xor_sync(0xFFFFFFFFu, r0, 2);
            r1 += __shfl_xor_sync(0xFFFFFFFFu, r1, 1);
            r1 += __shfl_xor_sync(0xFFFFFFFFu, r1, 2);
            if (t4 == 0) {
                int row = rowBase + warp_m * 64 + mi * 16 + g;
                atomicAdd(&d_r[b * NP + row], r0);
                atomicAdd(&d_r[b * NP + row + 8], r1);
            }
        }
    }
    if (job == 0 || job == 2) {
        #pragma unroll
        for (int ni = 0; ni < 4; ni++) {
            float c0 = cs[ni][0], c1 = cs[ni][1];
            c0 += __shfl_xor_sync(0xFFFFFFFFu, c0, 4);
            c0 += __shfl_xor_sync(0xFFFFFFFFu, c0, 8);
            c0 += __shfl_xor_sync(0xFFFFFFFFu, c0, 16);
            c1 += __shfl_xor_sync(0xFFFFFFFFu, c1, 4);
            c1 += __shfl_xor_sync(0xFFFFFFFFu, c1, 8);
            c1 += __shfl_xor_sync(0xFFFFFFFFu, c1, 16);
            if (lane < 4) {
                int col = colBase + warp_n * 32 + ni * 8 + lane * 2;
                atomicAdd(&d_c[b * NP + col], c0);
                atomicAdd(&d_c[b * NP + col + 1], c1);
            }
        }
    }
}

// ================= finalize: S(fp16) -> u16 Cq/CTq + fused init sums =================
__global__ void finalize_kernel() {
    __shared__ unsigned short tile[64][74];
    __shared__ float scol[64];
    int b = blockIdx.z;
    int pBase = blockIdx.y * 64, qBase = blockIdx.x * 64;
    int tid = threadIdx.x;  // 256
    int lane = tid & 31;
    const float NK9 = -0.16029948f;   // -log2(e)/9
    float cpart[4] = {0.f, 0.f, 0.f, 0.f};
    float rpart[4];
    if (tid < 64) scol[tid] = 0.f;
    __syncthreads();
    #pragma unroll
    for (int v = 0; v < 4; v++) {
        int f4 = v * 256 + tid;
        int row = f4 >> 4;
        int c4 = f4 & 15;
        int p = pBase + row;
        size_t idx = ((size_t)b * NP + p) * NP + qBase + c4 * 4;
        uint2 sh = *(const uint2*)(d_Sh + idx);
        float2 s01 = __half22float2(*(__half2*)&sh.x);
        float2 s23 = __half22float2(*(__half2*)&sh.y);
        float rp = d_r[b * NP + p];
        float4 cq = *(const float4*)(d_c + b * NP + qBase + c4 * 4);
        float4 C;
        C.x = 1.f - __fdividef(s01.x, rp + cq.x - s01.x);
        C.y = 1.f - __fdividef(s01.y, rp + cq.y - s01.y);
        C.z = 1.f - __fdividef(s23.x, rp + cq.z - s23.x);
        C.w = 1.f - __fdividef(s23.y, rp + cq.w - s23.y);
        ushort4 q = make_ushort4(quant(C.x), quant(C.y), quant(C.z), quant(C.w));
        *(ushort4*)(d_Cq + idx) = q;
        ((ushort2*)&tile[row][c4 * 4])[0] = make_ushort2(q.x, q.y);
        ((ushort2*)&tile[row][c4 * 4])[1] = make_ushort2(q.z, q.w);
        float e0 = exp2f(C.x * NK9);
        float e1 = exp2f(C.y * NK9);
        float e2 = exp2f(C.z * NK9);
        float e3 = exp2f(C.w * NK9);
        rpart[v] = (e0 + e1) + (e2 + e3);
        cpart[0] += e0; cpart[1] += e1; cpart[2] += e2; cpart[3] += e3;
    }
    #pragma unroll
    for (int v = 0; v < 4; v++) {
        float r = rpart[v];
        r += __shfl_xor_sync(0xFFFFFFFFu, r, 1);
        r += __shfl_xor_sync(0xFFFFFFFFu, r, 2);
        r += __shfl_xor_sync(0xFFFFFFFFu, r, 4);
        r += __shfl_xor_sync(0xFFFFFFFFu, r, 8);
        if ((lane & 15) == 0)
            atomicAdd(&d_fs[b * NP + pBase + v * 16 + (tid >> 4)], r);
    }
    #pragma unroll
    for (int j = 0; j < 4; j++) {
        cpart[j] += __shfl_xor_sync(0xFFFFFFFFu, cpart[j], 16);
        if (lane < 16) atomicAdd(&scol[lane * 4 + j], cpart[j]);
    }
    __syncthreads();
    if (tid < 64) atomicAdd(&d_gs[b * NP + qBase + tid], scol[tid]);

    int q = tid >> 2;
    int sbase = tid & 3;
    #pragma unroll
    for (int cc0 = 0; cc0 < 2; cc0++) {
        int cc = sbase + cc0 * 4;
        int p0 = cc * 8;
        unsigned short v16[8];
        #pragma unroll
        for (int i = 0; i < 8; i++) v16[i] = tile[p0 + i][q];
        uint4 o;
        o.x = (uint32_t)v16[0] | ((uint32_t)v16[1] << 16);
        o.y = (uint32_t)v16[2] | ((uint32_t)v16[3] << 16);
        o.z = (uint32_t)v16[4] | ((uint32_t)v16[5] << 16);
        o.w = (uint32_t)v16[6] | ((uint32_t)v16[7] << 16);
        *(uint4*)(d_CTq + ((size_t)b * NP + qBase + q) * NP + pBase + p0) = o;
    }
}

// ================= fused softmin: 2 rows/warp, h cached in smem =================
// UMAX=1 uses single-pass ONLINE logsumexp (no second row read)
template <int INIT, int UMAX>
__global__ void softmin_kernel(int src, int dst, float eps, int mode) {
    __shared__ float hs[NP];
    __shared__ double blkred[8];
    int bx = blockIdx.x;          // 1024 blocks
    int slice = bx >> 6;
    int side = slice >> 3;
    int b = slice & 7;
    int rowgrp = bx & 63;
    int tid = threadIdx.x;
    int wid = tid >> 5, lane = tid & 31;

    float k2 = 1.4426950408889634f / eps;
    float qk = -IQSCALE * k2;
    const float* hsrc = (side == 0 ? (INIT ? d_gs : d_g[src])
                                   : (INIT ? d_fs : d_f[src])) + b * NP;
    for (int i = tid; i < NP; i += 256) {
        float h = hsrc[i];
        if (INIT) h = -9.0f * __logf(h);
        hs[i] = h * k2;
    }
    __syncthreads();

    int row0 = rowgrp * 16 + wid * 2;
    int idxA = b * NP + row0;
    const unsigned short* Cb = (side == 0 ? d_Cq : d_CTq);
    const uint4* rA = (const uint4*)(Cb + ((size_t)b * NP + row0) * NP);
    const uint4* rB = (const uint4*)(Cb + ((size_t)b * NP + row0 + 1) * NP);
    const float4* h4 = (const float4*)hs;

    float mA = 0.f, mB = 0.f;        // running maxima (0 when !UMAX)
    float sA0 = 0, sA1 = 0, sB0 = 0, sB1 = 0;
    if (UMAX) { mA = -3.4e38f; mB = -3.4e38f; }

    #pragma unroll
    for (int jj = 0; jj < 4; jj++) {
        uint4 qa = rA[jj * 32 + lane];
        uint4 qb = rB[jj * 32 + lane];
        float4 h0 = h4[(jj * 32 + lane) * 2];
        float4 h1 = h4[(jj * 32 + lane) * 2 + 1];
        float tA[8], tB[8];
        tA[0] = fmaf((float)(qa.x & 0xFFFF), qk, h0.x);
        tB[0] = fmaf((float)(qb.x & 0xFFFF), qk, h0.x);
        tA[1] = fmaf((float)(qa.x >> 16),    qk, h0.y);
        tB[1] = fmaf((float)(qb.x >> 16),    qk, h0.y);
        tA[2] = fmaf((float)(qa.y & 0xFFFF), qk, h0.z);
        tB[2] = fmaf((float)(qb.y & 0xFFFF), qk, h0.z);
        tA[3] = fmaf((float)(qa.y >> 16),    qk, h0.w);
        tB[3] = fmaf((float)(qb.y >> 16),    qk, h0.w);
        tA[4] = fmaf((float)(qa.z & 0xFFFF), qk, h1.x);
        tB[4] = fmaf((float)(qb.z & 0xFFFF), qk, h1.x);
        tA[5] = fmaf((float)(qa.z >> 16),    qk, h1.y);
        tB[5] = fmaf((float)(qb.z >> 16),    qk, h1.y);
        tA[6] = fmaf((float)(qa.w & 0xFFFF), qk, h1.z);
        tB[6] = fmaf((float)(qb.w & 0xFFFF), qk, h1.z);
        tA[7] = fmaf((float)(qa.w >> 16),    qk, h1.w);
        tB[7] = fmaf((float)(qb.w >> 16),    qk, h1.w);
        if (UMAX) {
            float lA = fmaxf(fmaxf(fmaxf(tA[0], tA[1]), fmaxf(tA[2], tA[3])),
                             fmaxf(fmaxf(tA[4], tA[5]), fmaxf(tA[6], tA[7])));
            float lB = fmaxf(fmaxf(fmaxf(tB[0], tB[1]), fmaxf(tB[2], tB[3])),
                             fmaxf(fmaxf(tB[4], tB[5]), fmaxf(tB[6], tB[7])));
            float nA = fmaxf(mA, lA);
            float nB = fmaxf(mB, lB);
            float scA = exp2f(mA - nA);     // ==1 when unchanged; ==0 from -inf
            float scB = exp2f(mB - nB);
            sA0 *= scA; sA1 *= scA;
            sB0 *= scB; sB1 *= scB;
            mA = nA; mB = nB;
        }
        sA0 += exp2f(tA[0] - mA) + exp2f(tA[2] - mA) + exp2f(tA[4] - mA) + exp2f(tA[6] - mA);
        sA1 += exp2f(tA[1] - mA) + exp2f(tA[3] - mA) + exp2f(tA[5] - mA) + exp2f(tA[7] - mA);
        sB0 += exp2f(tB[0] - mB) + exp2f(tB[2] - mB) + exp2f(tB[4] - mB) + exp2f(tB[6] - mB);
        sB1 += exp2f(tB[1] - mB) + exp2f(tB[3] - mB) + exp2f(tB[5] - mB) + exp2f(tB[7] - mB);
    }
    float sumA = sA0 + sA1;
    float sumB = sB0 + sB1;

    if (UMAX) {
        // cross-lane (m, s) merge
        #pragma unroll
        for (int o = 16; o; o >>= 1) {
            float moA = __shfl_xor_sync(0xFFFFFFFFu, mA, o);
            float soA = __shfl_xor_sync(0xFFFFFFFFu, sumA, o);
            float moB = __shfl_xor_sync(0xFFFFFFFFu, mB, o);
            float soB = __shfl_xor_sync(0xFFFFFFFFu, sumB, o);
            float nA = fmaxf(mA, moA);
            float nB = fmaxf(mB, moB);
            sumA = sumA * exp2f(mA - nA) + soA * exp2f(moA - nA);
            sumB = sumB * exp2f(mB - nB) + soB * exp2f(moB - nB);
            mA = nA; mB = nB;
        }
    } else {
        #pragma unroll
        for (int o = 16; o; o >>= 1) {
            sumA += __shfl_xor_sync(0xFFFFFFFFu, sumA, o);
            sumB += __shfl_xor_sync(0xFFFFFFFFu, sumB, o);
        }
    }

    const float ELN2 = 0.69314718055994531f;
    if (mode == 2) {
        if (lane == 0) {
            float vA = -eps * ELN2 * (mA + __log2f(sumA));
            float vB = -eps * ELN2 * (mB + __log2f(sumB));
            blkred[wid] = (double)(vA + vB);
        }
        __syncthreads();
        if (tid == 0) {
            double t = ((blkred[0] + blkred[1]) + (blkred[2] + blkred[3]))
                     + ((blkred[4] + blkred[5]) + (blkred[6] + blkred[7]));
            atomicAdd(&d_scon, t);
        }
    } else if (lane == 0) {
        float vA = -eps * ELN2 * (mA + __log2f(sumA));
        float vB = -eps * ELN2 * (mB + __log2f(sumB));
        float pA, pB;
        if (INIT) {
            const float* ps = (side == 0 ? d_fs : d_gs);
            pA = -9.0f * __logf(ps[idxA]);
            pB = -9.0f * __logf(ps[idxA + 1]);
        } else {
            const float* ps = (side == 0 ? d_f[src] : d_g[src]);
            pA = ps[idxA];
            pB = ps[idxA + 1];
        }
        float* pd = (side == 0 ? d_f[dst] : d_g[dst]);
        pd[idxA]     = 0.5f * (pA + vA);
        pd[idxA + 1] = 0.5f * (pB + vB);
    }
}

// ================= output =================
__global__ void write_out(float* out) {
    if (threadIdx.x == 0) {
        out[0] = (float)d_hinge;
        out[1] = (float)(d_scon / 8.0);
    }
}

// ================= launch =================
extern "C" void kernel_launch(void* const* d_in, const int* in_sizes, int n_in,
                              void* d_out, int out_size) {
    (void)in_sizes; (void)n_in; (void)out_size;
    const float* x1 = (const float*)d_in[0];
    const float* x2 = (const float*)d_in[1];
    const float* x3 = (const float*)d_in[2];
    const float* x4 = (const float*)d_in[3];
    float* out = (float*)d_out;

    double pexp = 2.0, diam = 3.0, blur = 0.05, scal = 0.5;
    float eps_list[16];
    int n_eps = 0;
    eps_list[n_eps++] = (float)pow(diam, pexp);
    for (double v = pexp * log(diam); v > pexp * log(blur); v += pexp * log(scal))
        eps_list[n_eps++] = (float)exp(v);
    eps_list[n_eps++] = (float)pow(blur, pexp);   // n_eps == 8

    cudaFuncSetAttribute(mma_gemm, cudaFuncAttributeMaxDynamicSharedMemorySize, SM_TOT);

    norm_split<<<6145, 256>>>(x1, x2, x3, x4);    // block 6144 = reset

    mma_gemm<<<dim3(8, 8, 32), 256, SM_TOT>>>();

    finalize_kernel<<<dim3(16, 16, NB), 256>>>(); // also produces init sums

    int cur = 0;
    for (int i = 0; i < n_eps; i++) {
        float eps = eps_list[i];
        bool um = (eps < 0.02f);
        if (i == 0)      softmin_kernel<1, 0><<<1024, 256>>>(cur, 1 - cur, eps, 1);
        else if (!um)    softmin_kernel<0, 0><<<1024, 256>>>(cur, 1 - cur, eps, 1);
        else             softmin_kernel<0, 1><<<1024, 256>>>(cur, 1 - cur, eps, 1);
        cur = 1 - cur;
    }
    softmin_kernel<0, 1><<<1024, 256>>>(cur, cur, eps_list[n_eps - 1], 2);

    write_out<<<1, 1>>>(out);
}